// round 13
// baseline (speedup 1.0000x reference)
#include <cuda_runtime.h>
#include <cstdint>

#define NAG   4096
#define TOPK  12
#define NSEL  13                 // extract 13, fix up ordering with real sqrt
#define NITEMS (NAG * TOPK)      // 49152
#define T1    256                // threads, streaming kernel
#define EPT   16                 // elements per thread = 4096/256
#define CCAP  256                // per-row candidate capacity

// fused MLP tiling: 128 items/block, 8m x 8i (B) / 4o x 8i (C) thread tiles
#define TILE_I 128               // items per block
#define HSTR   128               // row stride (floats); conflict-free mapping
#define SMEM_FLOATS ((64 + 128) * HSTR)
#define SMEM_BYTES  (SMEM_FLOATS * 4)   // 98,304 B dynamic -> 2 blocks/SM

#define U64MAX 0xFFFFFFFFFFFFFFFFULL
typedef unsigned long long u64;

__device__ int   g_topk_idx[NITEMS];
__device__ float g_W2t[64 * 128];        // [k][m]
__device__ float g_W3t[128 * 64];        // [k][o]
__device__ u64   g_cand[NAG * CCAP];     // 8 MB candidate buffer
__device__ int   g_cnt[NAG];

static __device__ __forceinline__ u64 u64min(u64 a, u64 b) { return (b < a) ? b : a; }

// ---- packed f32x2 helpers (bitwise identical to two scalar fmaf's) --------
static __device__ __forceinline__ u64 pk2(float lo, float hi) {
    u64 r;
    asm("mov.b64 %0, {%1, %2};" : "=l"(r) : "f"(lo), "f"(hi));
    return r;
}
static __device__ __forceinline__ u64 fma2(u64 a, u64 b, u64 c) {
    u64 d;
    asm("fma.rn.f32x2 %0, %1, %2, %3;" : "=l"(d) : "l"(a), "l"(b), "l"(c));
    return d;
}
static __device__ __forceinline__ float2 up2(u64 v) {
    float2 f;
    asm("mov.b64 {%0, %1}, %2;" : "=f"(f.x), "=f"(f.y) : "l"(v));
    return f;
}

// ---------------------------------------------------------------------------
// Kernel 1a: streaming candidate filter (proven round 12, unchanged).
// ---------------------------------------------------------------------------
__global__ void __launch_bounds__(T1) topk_filter_kernel(const float* __restrict__ x) {
    const int i    = blockIdx.x;
    const int tid  = threadIdx.x;
    const int w    = tid >> 5;
    const int lane = tid & 31;
    const float* row = x + (size_t)i * (NAG * 4);

    unsigned sb[EPT];
#pragma unroll
    for (int t = 0; t < EPT; ++t) {
        const int j = tid + t * T1;
        const float2 v = *reinterpret_cast<const float2*>(row + (size_t)j * 4);
        const float s = __fadd_rn(__fadd_rn(__fmul_rn(v.x, v.x), 1e-6f),
                                  __fadd_rn(__fmul_rn(v.y, v.y), 1e-6f));
        sb[t] = __float_as_uint(s);
    }

    unsigned mymin = sb[0];
#pragma unroll
    for (int t = 1; t < EPT; ++t) mymin = (sb[t] < mymin) ? sb[t] : mymin;

    __shared__ unsigned tmin16[16];
    __shared__ unsigned sthresh;
    __shared__ int      scnt;
    if (tid == 0) scnt = 0;

    unsigned h = mymin;
#pragma unroll
    for (int off = 1; off <= 8; off <<= 1) {
        const unsigned o = __shfl_xor_sync(0xffffffffu, h, off);
        h = (o < h) ? o : h;
    }
    if ((lane & 15) == 0) tmin16[w * 2 + (lane >> 4)] = h;
    __syncthreads();

    if (w == 0 && lane < 16) {
        const unsigned mx = __reduce_max_sync(0xFFFFu, tmin16[lane]);
        if (lane == 0) sthresh = mx;
    }
    __syncthreads();

    const unsigned thr = sthresh;
    u64* cand = g_cand + (size_t)i * CCAP;
#pragma unroll
    for (int t = 0; t < EPT; ++t) {
        if (sb[t] <= thr) {
            const int pos = atomicAdd(&scnt, 1);
            if (pos < CCAP)
                cand[pos] = ((u64)sb[t] << 32) | (unsigned)(tid + t * T1);
        }
    }
    __syncthreads();
    if (tid == 0) g_cnt[i] = scnt;
}

// ---------------------------------------------------------------------------
// Kernel 1b: one warp per row; 13 ascending extract-min passes + sqrt fixup
// (proven, unchanged).
// ---------------------------------------------------------------------------
__global__ void __launch_bounds__(256) topk_extract_kernel(const float* __restrict__ x) {
    const int tid  = threadIdx.x;
    const int lane = tid & 31;
    const int i    = blockIdx.x * 8 + (tid >> 5);
    const int n    = g_cnt[i];

    u64 fk[NSEL];
    u64 prev = 0;

    if (n <= CCAP) {
        const u64* cand = g_cand + (size_t)i * CCAP;
        u64 ck[8];
#pragma unroll
        for (int t = 0; t < 8; ++t) {
            const int idx = lane + t * 32;
            ck[t] = (idx < n) ? cand[idx] : U64MAX;
        }
#pragma unroll 1
        for (int pass = 0; pass < NSEL; ++pass) {
            u64 lmin = U64MAX;
#pragma unroll
            for (int t = 0; t < 8; ++t)
                if (ck[t] > prev) lmin = u64min(lmin, ck[t]);
            u64 v = lmin;
#pragma unroll
            for (int off = 16; off > 0; off >>= 1) {
                const u64 o = __shfl_xor_sync(0xffffffffu, v, off);
                v = u64min(v, o);
            }
            fk[pass] = v;
            prev = v;
        }
    } else {
        const float* row = x + (size_t)i * (NAG * 4);
#pragma unroll 1
        for (int pass = 0; pass < NSEL; ++pass) {
            u64 lmin = U64MAX;
            for (int t = 0; t < NAG / 32; ++t) {
                const int j = lane + t * 32;
                const float2 v2 = *reinterpret_cast<const float2*>(row + (size_t)j * 4);
                const float s = __fadd_rn(__fadd_rn(__fmul_rn(v2.x, v2.x), 1e-6f),
                                          __fadd_rn(__fmul_rn(v2.y, v2.y), 1e-6f));
                const u64 k = ((u64)__float_as_uint(s) << 32) | (unsigned)j;
                if (k > prev) lmin = u64min(lmin, k);
            }
            u64 v = lmin;
#pragma unroll
            for (int off = 16; off > 0; off >>= 1) {
                const u64 o = __shfl_xor_sync(0xffffffffu, v, off);
                v = u64min(v, o);
            }
            fk[pass] = v;
            prev = v;
        }
    }

    if (lane == 0) {
#pragma unroll
        for (int t = 0; t < NSEL; ++t) {
            const u64 k = fk[t];
            const float s  = __uint_as_float((unsigned)(k >> 32));
            const float dn = __fsqrt_rn(s);
            fk[t] = ((u64)__float_as_uint(dn) << 32) | (k & 0xFFFFFFFFULL);
        }
#pragma unroll
        for (int a = 1; a < NSEL; ++a) {
            const u64 key = fk[a];
            int b = a - 1;
#pragma unroll
            for (int q = 0; q < NSEL - 1; ++q) {
                if (b >= 0 && fk[b] > key) { fk[b + 1] = fk[b]; b--; }
            }
            fk[b + 1] = key;
        }
#pragma unroll
        for (int t = 0; t < TOPK; ++t)
            g_topk_idx[i * TOPK + t] = (int)(unsigned)(fk[t] & 0xFFFFFFFFULL);
    }
}

// ---------------------------------------------------------------------------
// Kernel T: transpose (parallel grid-stride)
// ---------------------------------------------------------------------------
__global__ void __launch_bounds__(256) transpose_kernel(
    const float* __restrict__ W2, const float* __restrict__ W3)
{
    const int g = blockIdx.x * 256 + threadIdx.x;
    const int stride = gridDim.x * 256;
    for (int s = g; s < 128 * 64; s += stride) {
        const int m = s >> 6, k = s & 63;
        g_W2t[k * 128 + m] = W2[s];
    }
    for (int s = g; s < 64 * 128; s += stride) {
        const int o = s >> 7, m = s & 127;
        g_W3t[m * 64 + o] = W3[s];
    }
}

// ---------------------------------------------------------------------------
// Fused MLP kernel: 128 items/block, 2 blocks/SM (96 KB smem).
// Stage B: thread = 8m x 8i (f32x2 on items, split {i0..i0+3}∪{i0+64..i0+67});
//          per k: 2 LDG.128 weights + 2 LDS.128 items feed 32 FFMA2.
// Stage C: thread = 4o x 8i, K=128; fused layer4 partial reduction.
// All smem accesses lane-contiguous -> conflict-free.
// ---------------------------------------------------------------------------
__global__ void __launch_bounds__(256, 2) fused_mlp_kernel(
    const float* __restrict__ x,  const float* __restrict__ rp,
    const float* __restrict__ W1, const float* __restrict__ b1,
    const float* __restrict__ b2, const float* __restrict__ b3,
    const float* __restrict__ W4, const float* __restrict__ b4,
    float* __restrict__ out)
{
    extern __shared__ float smem[];
    float* H1s = smem;                   // [64][HSTR]
    float* H2s = smem + 64 * HSTR;       // [128][HSTR]
    float* red = smem;                   // reuse H1s area in stage C epilogue

    __shared__ float W1s[64 * 6];
    __shared__ float b1s[64];
    __shared__ float masks[TILE_I];

    const int tid = threadIdx.x;
    for (int s = tid; s < 384; s += 256) W1s[s] = W1[s];
    if (tid < 64) b1s[tid] = b1[tid];
    __syncthreads();

    // ---------------- stage A: features + layer1 (6 -> 64) ----------------
    {
        const int iloc = tid & 127;          // 128 items
        const int q    = tid >> 7;           // 2 threads per item
        const int item = blockIdx.x * TILE_I + iloc;
        const int i = item / TOPK;
        const int j = g_topk_idx[item];

        const float4 v = *reinterpret_cast<const float4*>(
            x + ((size_t)i * NAG + (size_t)j) * 4);
        const float s2 = __fadd_rn(__fadd_rn(__fmul_rn(v.x, v.x), 1e-4f),
                                   __fadd_rn(__fmul_rn(v.y, v.y), 1e-4f));
        const float dn = __fsqrt_rn(s2);
        const float r  = rp[0];
        const float mk = (dn <= 1.0f) ? 1.0f : 0.0f;
        const float f0 = v.x, f1 = v.y, f2 = v.z, f3 = v.w;
        const float f4 = (i == j) ? 1.0f : 0.0f;
        const float f5 = dn - r;

        const int o0 = q * 32;
#pragma unroll
        for (int oo = 0; oo < 32; ++oo) {
            const int o = o0 + oo;
            const float* wp = W1s + o * 6;
            float a = b1s[o];
            a = fmaf(wp[0], f0, a); a = fmaf(wp[1], f1, a); a = fmaf(wp[2], f2, a);
            a = fmaf(wp[3], f3, a); a = fmaf(wp[4], f4, a); a = fmaf(wp[5], f5, a);
            H1s[o * HSTR + iloc] = fmaxf(a, 0.0f);
        }

        if (q == 0) {
            masks[iloc] = mk;
            out[NITEMS + item] = mk;
            out[2 * NITEMS + 2 * item + 0] = (float)i;
            out[2 * NITEMS + 2 * item + 1] = (float)j;
        }
    }
    __syncthreads();

    // ----- stage B: layer2 GEMM (K=64), 8m x (4+4 split) items, f32x2 ------
    {
        const int m0 = (tid >> 4) * 8;       // 0..120
        const int i0 = (tid & 15) * 4;       // 0..60; items i0..i0+3, i0+64..67

        u64 acc[8][4];                       // [m][pair]: p0,p1 low; p2,p3 high
#pragma unroll
        for (int mm = 0; mm < 8; ++mm) {
            const float b = b2[m0 + mm];
            const u64 pb = pk2(b, b);
#pragma unroll
            for (int p = 0; p < 4; ++p) acc[mm][p] = pb;
        }

#pragma unroll 2
        for (int k = 0; k < 64; ++k) {
            const float4 a0 = *reinterpret_cast<const float4*>(g_W2t + k * 128 + m0);
            const float4 a1 = *reinterpret_cast<const float4*>(g_W2t + k * 128 + m0 + 4);
            const ulonglong2 xa =
                *reinterpret_cast<const ulonglong2*>(H1s + k * HSTR + i0);
            const ulonglong2 xb =
                *reinterpret_cast<const ulonglong2*>(H1s + k * HSTR + i0 + 64);
            const u64 w0 = pk2(a0.x, a0.x);
            const u64 w1 = pk2(a0.y, a0.y);
            const u64 w2 = pk2(a0.z, a0.z);
            const u64 w3 = pk2(a0.w, a0.w);
            const u64 w4v = pk2(a1.x, a1.x);
            const u64 w5 = pk2(a1.y, a1.y);
            const u64 w6 = pk2(a1.z, a1.z);
            const u64 w7 = pk2(a1.w, a1.w);
            acc[0][0] = fma2(w0, xa.x, acc[0][0]); acc[0][1] = fma2(w0, xa.y, acc[0][1]);
            acc[0][2] = fma2(w0, xb.x, acc[0][2]); acc[0][3] = fma2(w0, xb.y, acc[0][3]);
            acc[1][0] = fma2(w1, xa.x, acc[1][0]); acc[1][1] = fma2(w1, xa.y, acc[1][1]);
            acc[1][2] = fma2(w1, xb.x, acc[1][2]); acc[1][3] = fma2(w1, xb.y, acc[1][3]);
            acc[2][0] = fma2(w2, xa.x, acc[2][0]); acc[2][1] = fma2(w2, xa.y, acc[2][1]);
            acc[2][2] = fma2(w2, xb.x, acc[2][2]); acc[2][3] = fma2(w2, xb.y, acc[2][3]);
            acc[3][0] = fma2(w3, xa.x, acc[3][0]); acc[3][1] = fma2(w3, xa.y, acc[3][1]);
            acc[3][2] = fma2(w3, xb.x, acc[3][2]); acc[3][3] = fma2(w3, xb.y, acc[3][3]);
            acc[4][0] = fma2(w4v, xa.x, acc[4][0]); acc[4][1] = fma2(w4v, xa.y, acc[4][1]);
            acc[4][2] = fma2(w4v, xb.x, acc[4][2]); acc[4][3] = fma2(w4v, xb.y, acc[4][3]);
            acc[5][0] = fma2(w5, xa.x, acc[5][0]); acc[5][1] = fma2(w5, xa.y, acc[5][1]);
            acc[5][2] = fma2(w5, xb.x, acc[5][2]); acc[5][3] = fma2(w5, xb.y, acc[5][3]);
            acc[6][0] = fma2(w6, xa.x, acc[6][0]); acc[6][1] = fma2(w6, xa.y, acc[6][1]);
            acc[6][2] = fma2(w6, xb.x, acc[6][2]); acc[6][3] = fma2(w6, xb.y, acc[6][3]);
            acc[7][0] = fma2(w7, xa.x, acc[7][0]); acc[7][1] = fma2(w7, xa.y, acc[7][1]);
            acc[7][2] = fma2(w7, xb.x, acc[7][2]); acc[7][3] = fma2(w7, xb.y, acc[7][3]);
        }

#pragma unroll
        for (int mm = 0; mm < 8; ++mm) {
            float* dst = H2s + (m0 + mm) * HSTR;
            const float2 p0 = up2(acc[mm][0]);
            const float2 p1 = up2(acc[mm][1]);
            const float2 p2 = up2(acc[mm][2]);
            const float2 p3 = up2(acc[mm][3]);
            float4 s0, s1;
            s0.x = fmaxf(p0.x, 0.f); s0.y = fmaxf(p0.y, 0.f);
            s0.z = fmaxf(p1.x, 0.f); s0.w = fmaxf(p1.y, 0.f);
            s1.x = fmaxf(p2.x, 0.f); s1.y = fmaxf(p2.y, 0.f);
            s1.z = fmaxf(p3.x, 0.f); s1.w = fmaxf(p3.y, 0.f);
            *reinterpret_cast<float4*>(dst + i0)      = s0;
            *reinterpret_cast<float4*>(dst + i0 + 64) = s1;
        }
    }
    __syncthreads();

    // ----- stage C: layer3 GEMM (K=128), 4o x (4+4 split) items + layer4 ---
    {
        const int o0 = (tid >> 4) * 4;       // 0..60
        const int i0 = (tid & 15) * 4;       // 0..60; items i0..i0+3, i0+64..67

        u64 acc[4][4];                       // [o][pair]
#pragma unroll
        for (int oo = 0; oo < 4; ++oo) {
            const float b = b3[o0 + oo];
            const u64 pb = pk2(b, b);
#pragma unroll
            for (int p = 0; p < 4; ++p) acc[oo][p] = pb;
        }

#pragma unroll 2
        for (int k = 0; k < 128; ++k) {
            const float4 a = *reinterpret_cast<const float4*>(g_W3t + k * 64 + o0);
            const ulonglong2 xa =
                *reinterpret_cast<const ulonglong2*>(H2s + k * HSTR + i0);
            const ulonglong2 xb =
                *reinterpret_cast<const ulonglong2*>(H2s + k * HSTR + i0 + 64);
            const u64 w0 = pk2(a.x, a.x);
            const u64 w1 = pk2(a.y, a.y);
            const u64 w2 = pk2(a.z, a.z);
            const u64 w3 = pk2(a.w, a.w);
            acc[0][0] = fma2(w0, xa.x, acc[0][0]); acc[0][1] = fma2(w0, xa.y, acc[0][1]);
            acc[0][2] = fma2(w0, xb.x, acc[0][2]); acc[0][3] = fma2(w0, xb.y, acc[0][3]);
            acc[1][0] = fma2(w1, xa.x, acc[1][0]); acc[1][1] = fma2(w1, xa.y, acc[1][1]);
            acc[1][2] = fma2(w1, xb.x, acc[1][2]); acc[1][3] = fma2(w1, xb.y, acc[1][3]);
            acc[2][0] = fma2(w2, xa.x, acc[2][0]); acc[2][1] = fma2(w2, xa.y, acc[2][1]);
            acc[2][2] = fma2(w2, xb.x, acc[2][2]); acc[2][3] = fma2(w2, xb.y, acc[2][3]);
            acc[3][0] = fma2(w3, xa.x, acc[3][0]); acc[3][1] = fma2(w3, xa.y, acc[3][1]);
            acc[3][2] = fma2(w3, xb.x, acc[3][2]); acc[3][3] = fma2(w3, xb.y, acc[3][3]);
        }

        // relu + partial layer4 dot over this thread's 4 o's -> red[16][item]
        const float4 w4 = *reinterpret_cast<const float4*>(W4 + o0);
        const int og = tid >> 4;             // 0..15

        float4 pa, pb;
        {
            const float2 v00 = up2(acc[0][0]); const float2 v01 = up2(acc[0][1]);
            const float2 v10 = up2(acc[1][0]); const float2 v11 = up2(acc[1][1]);
            const float2 v20 = up2(acc[2][0]); const float2 v21 = up2(acc[2][1]);
            const float2 v30 = up2(acc[3][0]); const float2 v31 = up2(acc[3][1]);
            pa.x = __fmul_rn(w4.x, fmaxf(v00.x, 0.f));
            pa.x = fmaf(w4.y, fmaxf(v10.x, 0.f), pa.x);
            pa.x = fmaf(w4.z, fmaxf(v20.x, 0.f), pa.x);
            pa.x = fmaf(w4.w, fmaxf(v30.x, 0.f), pa.x);
            pa.y = __fmul_rn(w4.x, fmaxf(v00.y, 0.f));
            pa.y = fmaf(w4.y, fmaxf(v10.y, 0.f), pa.y);
            pa.y = fmaf(w4.z, fmaxf(v20.y, 0.f), pa.y);
            pa.y = fmaf(w4.w, fmaxf(v30.y, 0.f), pa.y);
            pa.z = __fmul_rn(w4.x, fmaxf(v01.x, 0.f));
            pa.z = fmaf(w4.y, fmaxf(v11.x, 0.f), pa.z);
            pa.z = fmaf(w4.z, fmaxf(v21.x, 0.f), pa.z);
            pa.z = fmaf(w4.w, fmaxf(v31.x, 0.f), pa.z);
            pa.w = __fmul_rn(w4.x, fmaxf(v01.y, 0.f));
            pa.w = fmaf(w4.y, fmaxf(v11.y, 0.f), pa.w);
            pa.w = fmaf(w4.z, fmaxf(v21.y, 0.f), pa.w);
            pa.w = fmaf(w4.w, fmaxf(v31.y, 0.f), pa.w);
        }
        {
            const float2 v02 = up2(acc[0][2]); const float2 v03 = up2(acc[0][3]);
            const float2 v12 = up2(acc[1][2]); const float2 v13 = up2(acc[1][3]);
            const float2 v22 = up2(acc[2][2]); const float2 v23 = up2(acc[2][3]);
            const float2 v32 = up2(acc[3][2]); const float2 v33 = up2(acc[3][3]);
            pb.x = __fmul_rn(w4.x, fmaxf(v02.x, 0.f));
            pb.x = fmaf(w4.y, fmaxf(v12.x, 0.f), pb.x);
            pb.x = fmaf(w4.z, fmaxf(v22.x, 0.f), pb.x);
            pb.x = fmaf(w4.w, fmaxf(v32.x, 0.f), pb.x);
            pb.y = __fmul_rn(w4.x, fmaxf(v02.y, 0.f));
            pb.y = fmaf(w4.y, fmaxf(v12.y, 0.f), pb.y);
            pb.y = fmaf(w4.z, fmaxf(v22.y, 0.f), pb.y);
            pb.y = fmaf(w4.w, fmaxf(v32.y, 0.f), pb.y);
            pb.z = __fmul_rn(w4.x, fmaxf(v03.x, 0.f));
            pb.z = fmaf(w4.y, fmaxf(v13.x, 0.f), pb.z);
            pb.z = fmaf(w4.z, fmaxf(v23.x, 0.f), pb.z);
            pb.z = fmaf(w4.w, fmaxf(v33.x, 0.f), pb.z);
            pb.w = __fmul_rn(w4.x, fmaxf(v03.y, 0.f));
            pb.w = fmaf(w4.y, fmaxf(v13.y, 0.f), pb.w);
            pb.w = fmaf(w4.z, fmaxf(v23.y, 0.f), pb.w);
            pb.w = fmaf(w4.w, fmaxf(v33.y, 0.f), pb.w);
        }

        // red aliases H1s (dead after stage B); stage C reads only H2s -> safe
        *reinterpret_cast<float4*>(red + og * HSTR + i0)      = pa;
        *reinterpret_cast<float4*>(red + og * HSTR + i0 + 64) = pb;
    }
    __syncthreads();

    // final: one thread per item sums 16 partials
    if (tid < TILE_I) {
        const int item = blockIdx.x * TILE_I + tid;
        float s = red[tid];
#pragma unroll
        for (int g = 1; g < 16; ++g) s += red[g * HSTR + tid];
        out[item] = (s + b4[0]) * masks[tid];
    }
}

extern "C" void kernel_launch(void* const* d_in, const int* in_sizes, int n_in,
                              void* d_out, int out_size) {
    const float* x  = (const float*)d_in[0];
    const float* r  = (const float*)d_in[1];
    const float* W1 = (const float*)d_in[2];
    const float* b1 = (const float*)d_in[3];
    const float* W2 = (const float*)d_in[4];
    const float* b2 = (const float*)d_in[5];
    const float* W3 = (const float*)d_in[6];
    const float* b3 = (const float*)d_in[7];
    const float* W4 = (const float*)d_in[8];
    const float* b4 = (const float*)d_in[9];
    float* out = (float*)d_out;

    cudaFuncSetAttribute(fused_mlp_kernel,
                         cudaFuncAttributeMaxDynamicSharedMemorySize, SMEM_BYTES);

    topk_filter_kernel<<<NAG, T1>>>(x);
    topk_extract_kernel<<<NAG / 8, 256>>>(x);
    transpose_kernel<<<32, 256>>>(W2, W3);
    fused_mlp_kernel<<<NITEMS / TILE_I, 256, SMEM_BYTES>>>(
        x, r, W1, b1, b2, b3, W4, b4, out);
}

// round 14
// speedup vs baseline: 1.1589x; 1.1589x over previous
#include <cuda_runtime.h>
#include <cstdint>

#define NAG   4096
#define TOPK  12
#define NSEL  13                 // extract 13, fix up ordering with real sqrt
#define NITEMS (NAG * TOPK)      // 49152
#define T1    256                // threads, streaming kernel
#define EPT   16                 // elements per thread = 4096/256
#define CCAP  256                // per-row candidate capacity (smem)
#define TGRID 32                 // transpose helper blocks appended to grid

// fused MLP tiling (round-12 proven geometry, conflict-free item mapping)
#define TILE_I 64                // items per block
#define HSTR   68                // padded row stride (floats)
#define SMEM_FLOATS ((64 + 128) * HSTR)
#define SMEM_BYTES  (SMEM_FLOATS * 4)   // 52,224 B dynamic -> 3 blocks/SM

#define U64MAX 0xFFFFFFFFFFFFFFFFULL
typedef unsigned long long u64;

__device__ int   g_topk_idx[NITEMS];
__device__ float g_W2t[64 * 128];        // [k][m]
__device__ float g_W3t[128 * 64];        // [k][o]

static __device__ __forceinline__ u64 u64min(u64 a, u64 b) { return (b < a) ? b : a; }

// ---- packed f32x2 helpers (bitwise identical to two scalar fmaf's) --------
static __device__ __forceinline__ u64 pk2(float lo, float hi) {
    u64 r;
    asm("mov.b64 %0, {%1, %2};" : "=l"(r) : "f"(lo), "f"(hi));
    return r;
}
static __device__ __forceinline__ u64 fma2(u64 a, u64 b, u64 c) {
    u64 d;
    asm("fma.rn.f32x2 %0, %1, %2, %3;" : "=l"(d) : "l"(a), "l"(b), "l"(c));
    return d;
}
static __device__ __forceinline__ float2 up2(u64 v) {
    float2 f;
    asm("mov.b64 {%0, %1}, %2;" : "=f"(f.x), "=f"(f.y) : "l"(v));
    return f;
}

// ---------------------------------------------------------------------------
// Kernel 1: fused filter + extract (+ appended transpose blocks).
//  blocks [0,NAG): per-row streaming filter -> smem candidate buffer ->
//    warp-0 13-pass extract-min + sqrt fixup -> g_topk_idx (no global cand).
//  blocks [NAG,NAG+TGRID): transpose W2 -> g_W2t, W3 -> g_W3t.
// Threshold = max of 16 half-warp minima (16 disjoint groups) => at least 16
// elements <= thr, so 13 extraction passes always have real candidates.
// Overflow (n > CCAP, nondeterministic subset) falls back to a deterministic
// full-row rescan. sqrt_rn is monotone: re-keying the top-13 by
// (sqrt_bits, j) and keeping 12 reproduces reference tie-breaking exactly.
// ---------------------------------------------------------------------------
__global__ void __launch_bounds__(T1) topk_fused_kernel(
    const float* __restrict__ x,
    const float* __restrict__ W2, const float* __restrict__ W3)
{
    const int tid  = threadIdx.x;

    if (blockIdx.x >= NAG) {             // ---- transpose service blocks ----
        const int g = (blockIdx.x - NAG) * T1 + tid;
        const int stride = TGRID * T1;
        for (int s = g; s < 128 * 64; s += stride) {
            const int m = s >> 6, k = s & 63;
            g_W2t[k * 128 + m] = W2[s];
        }
        for (int s = g; s < 64 * 128; s += stride) {
            const int o = s >> 7, m = s & 127;
            g_W3t[m * 64 + o] = W3[s];
        }
        return;
    }

    const int i    = blockIdx.x;
    const int w    = tid >> 5;
    const int lane = tid & 31;
    const float* row = x + (size_t)i * (NAG * 4);

    unsigned sb[EPT];
#pragma unroll
    for (int t = 0; t < EPT; ++t) {
        const int j = tid + t * T1;
        const float2 v = __ldcs(reinterpret_cast<const float2*>(row + (size_t)j * 4));
        const float s = __fadd_rn(__fadd_rn(__fmul_rn(v.x, v.x), 1e-6f),
                                  __fadd_rn(__fmul_rn(v.y, v.y), 1e-6f));
        sb[t] = __float_as_uint(s);
    }

    unsigned mymin = sb[0];
#pragma unroll
    for (int t = 1; t < EPT; ++t) mymin = (sb[t] < mymin) ? sb[t] : mymin;

    __shared__ unsigned tmin16[16];
    __shared__ unsigned sthresh;
    __shared__ int      scnt;
    __shared__ u64      scand[CCAP];
    if (tid == 0) scnt = 0;

    // half-warp minima via shuffles (offsets 1,2,4,8 stay within 16 lanes)
    unsigned h = mymin;
#pragma unroll
    for (int off = 1; off <= 8; off <<= 1) {
        const unsigned o = __shfl_xor_sync(0xffffffffu, h, off);
        h = (o < h) ? o : h;
    }
    if ((lane & 15) == 0) tmin16[w * 2 + (lane >> 4)] = h;
    __syncthreads();

    if (w == 0 && lane < 16) {
        const unsigned mx = __reduce_max_sync(0xFFFFu, tmin16[lane]);
        if (lane == 0) sthresh = mx;
    }
    __syncthreads();

    const unsigned thr = sthresh;
#pragma unroll
    for (int t = 0; t < EPT; ++t) {
        if (sb[t] <= thr) {
            const int pos = atomicAdd(&scnt, 1);
            if (pos < CCAP)
                scand[pos] = ((u64)sb[t] << 32) | (unsigned)(tid + t * T1);
        }
    }
    __syncthreads();

    // ---- fused extract tail: warp 0 only (other warps done) ----
    if (w != 0) return;

    const int n = scnt;
    u64 fk[NSEL];
    u64 prev = 0;                        // keys >= 2^32 > 0

    if (n <= CCAP) {
        u64 ck[CCAP / 32];               // 8 per lane
#pragma unroll
        for (int t = 0; t < CCAP / 32; ++t) {
            const int idx = lane + t * 32;
            ck[t] = (idx < n) ? scand[idx] : U64MAX;
        }
#pragma unroll 1
        for (int pass = 0; pass < NSEL; ++pass) {
            u64 lmin = U64MAX;
#pragma unroll
            for (int t = 0; t < CCAP / 32; ++t)
                if (ck[t] > prev) lmin = u64min(lmin, ck[t]);
            u64 v = lmin;
#pragma unroll
            for (int off = 16; off > 0; off >>= 1) {
                const u64 o = __shfl_xor_sync(0xffffffffu, v, off);
                v = u64min(v, o);
            }
            fk[pass] = v;
            prev = v;
        }
    } else {
        // overflow fallback: deterministic full-row rescan (rare/never)
#pragma unroll 1
        for (int pass = 0; pass < NSEL; ++pass) {
            u64 lmin = U64MAX;
            for (int t = 0; t < NAG / 32; ++t) {
                const int j = lane + t * 32;
                const float2 v2 = *reinterpret_cast<const float2*>(row + (size_t)j * 4);
                const float s = __fadd_rn(__fadd_rn(__fmul_rn(v2.x, v2.x), 1e-6f),
                                          __fadd_rn(__fmul_rn(v2.y, v2.y), 1e-6f));
                const u64 k = ((u64)__float_as_uint(s) << 32) | (unsigned)j;
                if (k > prev) lmin = u64min(lmin, k);
            }
            u64 v = lmin;
#pragma unroll
            for (int off = 16; off > 0; off >>= 1) {
                const u64 o = __shfl_xor_sync(0xffffffffu, v, off);
                v = u64min(v, o);
            }
            fk[pass] = v;
            prev = v;
        }
    }

    // fixup on lane 0: re-key by (sqrt_bits, j), insertion sort, keep 12
    if (lane == 0) {
#pragma unroll
        for (int t = 0; t < NSEL; ++t) {
            const u64 k = fk[t];
            const float s  = __uint_as_float((unsigned)(k >> 32));
            const float dn = __fsqrt_rn(s);
            fk[t] = ((u64)__float_as_uint(dn) << 32) | (k & 0xFFFFFFFFULL);
        }
#pragma unroll
        for (int a = 1; a < NSEL; ++a) {
            const u64 key = fk[a];
            int b = a - 1;
#pragma unroll
            for (int q = 0; q < NSEL - 1; ++q) {
                if (b >= 0 && fk[b] > key) { fk[b + 1] = fk[b]; b--; }
            }
            fk[b + 1] = key;
        }
#pragma unroll
        for (int t = 0; t < TOPK; ++t)
            g_topk_idx[i * TOPK + t] = (int)(unsigned)(fk[t] & 0xFFFFFFFFULL);
    }
}

// ---------------------------------------------------------------------------
// Fused MLP kernel: EXACT round-12 winner (64 items/block, 3 blocks/SM,
// f32x2, conflict-free split item mapping {i0..i0+3} U {i0+32..i0+35}).
// ---------------------------------------------------------------------------
__global__ void __launch_bounds__(256, 3) fused_mlp_kernel(
    const float* __restrict__ x,  const float* __restrict__ rp,
    const float* __restrict__ W1, const float* __restrict__ b1,
    const float* __restrict__ b2, const float* __restrict__ b3,
    const float* __restrict__ W4, const float* __restrict__ b4,
    float* __restrict__ out)
{
    extern __shared__ float smem[];
    float* H1s = smem;                   // [64][HSTR]
    float* H2s = smem + 64 * HSTR;       // [128][HSTR]
    float* red = smem;                   // reuse H1s area in stage C epilogue

    __shared__ float W1s[64 * 6];
    __shared__ float b1s[64];
    __shared__ float masks[TILE_I];

    const int tid = threadIdx.x;
    for (int s = tid; s < 384; s += 256) W1s[s] = W1[s];
    if (tid < 64) b1s[tid] = b1[tid];
    __syncthreads();

    // ---------------- stage A: features + layer1 (6 -> 64) ----------------
    {
        const int iloc = tid & 63;
        const int q    = tid >> 6;           // 4 threads per item
        const int item = blockIdx.x * TILE_I + iloc;
        const int i = item / TOPK;
        const int j = g_topk_idx[item];

        const float4 v = *reinterpret_cast<const float4*>(
            x + ((size_t)i * NAG + (size_t)j) * 4);
        const float s2 = __fadd_rn(__fadd_rn(__fmul_rn(v.x, v.x), 1e-4f),
                                   __fadd_rn(__fmul_rn(v.y, v.y), 1e-4f));
        const float dn = __fsqrt_rn(s2);
        const float r  = rp[0];
        const float mk = (dn <= 1.0f) ? 1.0f : 0.0f;
        const float f0 = v.x, f1 = v.y, f2 = v.z, f3 = v.w;
        const float f4 = (i == j) ? 1.0f : 0.0f;
        const float f5 = dn - r;

        const int o0 = q * 16;
#pragma unroll
        for (int oo = 0; oo < 16; ++oo) {
            const int o = o0 + oo;
            const float* wp = W1s + o * 6;
            float a = b1s[o];
            a = fmaf(wp[0], f0, a); a = fmaf(wp[1], f1, a); a = fmaf(wp[2], f2, a);
            a = fmaf(wp[3], f3, a); a = fmaf(wp[4], f4, a); a = fmaf(wp[5], f5, a);
            H1s[o * HSTR + iloc] = fmaxf(a, 0.0f);
        }

        if (q == 0) {
            masks[iloc] = mk;
            out[NITEMS + item] = mk;
            out[2 * NITEMS + 2 * item + 0] = (float)i;
            out[2 * NITEMS + 2 * item + 1] = (float)j;
        }
    }
    __syncthreads();

    // ----- stage B: layer2 GEMM (K=64), 4m x (4+4 split) items, f32x2 ------
    {
        const int m0 = (tid >> 3) * 4;       // 0..124
        const int i0 = (tid & 7) * 4;        // 0..28; items i0..i0+3, i0+32..35

        u64 acc[4][4];                       // [m][pair]: p0,p1=i0 side; p2,p3=+32
#pragma unroll
        for (int mm = 0; mm < 4; ++mm) {
            const float b = b2[m0 + mm];
            const u64 pb = pk2(b, b);
            acc[mm][0] = pb; acc[mm][1] = pb; acc[mm][2] = pb; acc[mm][3] = pb;
        }

#pragma unroll 4
        for (int k = 0; k < 64; ++k) {
            const float4 a = *reinterpret_cast<const float4*>(g_W2t + k * 128 + m0);
            const ulonglong2 xa =
                *reinterpret_cast<const ulonglong2*>(H1s + k * HSTR + i0);
            const ulonglong2 xb =
                *reinterpret_cast<const ulonglong2*>(H1s + k * HSTR + i0 + 32);
            const u64 ax = pk2(a.x, a.x);
            const u64 ay = pk2(a.y, a.y);
            const u64 az = pk2(a.z, a.z);
            const u64 aw = pk2(a.w, a.w);
            acc[0][0] = fma2(ax, xa.x, acc[0][0]); acc[0][1] = fma2(ax, xa.y, acc[0][1]);
            acc[0][2] = fma2(ax, xb.x, acc[0][2]); acc[0][3] = fma2(ax, xb.y, acc[0][3]);
            acc[1][0] = fma2(ay, xa.x, acc[1][0]); acc[1][1] = fma2(ay, xa.y, acc[1][1]);
            acc[1][2] = fma2(ay, xb.x, acc[1][2]); acc[1][3] = fma2(ay, xb.y, acc[1][3]);
            acc[2][0] = fma2(az, xa.x, acc[2][0]); acc[2][1] = fma2(az, xa.y, acc[2][1]);
            acc[2][2] = fma2(az, xb.x, acc[2][2]); acc[2][3] = fma2(az, xb.y, acc[2][3]);
            acc[3][0] = fma2(aw, xa.x, acc[3][0]); acc[3][1] = fma2(aw, xa.y, acc[3][1]);
            acc[3][2] = fma2(aw, xb.x, acc[3][2]); acc[3][3] = fma2(aw, xb.y, acc[3][3]);
        }

#pragma unroll
        for (int mm = 0; mm < 4; ++mm) {
            float* dst = H2s + (m0 + mm) * HSTR;
            const float2 p0 = up2(acc[mm][0]);
            const float2 p1 = up2(acc[mm][1]);
            const float2 p2 = up2(acc[mm][2]);
            const float2 p3 = up2(acc[mm][3]);
            float4 s0, s1;
            s0.x = fmaxf(p0.x, 0.f); s0.y = fmaxf(p0.y, 0.f);
            s0.z = fmaxf(p1.x, 0.f); s0.w = fmaxf(p1.y, 0.f);
            s1.x = fmaxf(p2.x, 0.f); s1.y = fmaxf(p2.y, 0.f);
            s1.z = fmaxf(p3.x, 0.f); s1.w = fmaxf(p3.y, 0.f);
            *reinterpret_cast<float4*>(dst + i0)      = s0;   // conflict-free
            *reinterpret_cast<float4*>(dst + i0 + 32) = s1;   // conflict-free
        }
    }
    __syncthreads();

    // ----- stage C: layer3 GEMM (K=128), 4o x (2+2 split) items + layer4 ---
    {
        const int o0 = (tid >> 4) * 4;       // 0..60
        const int c  = (tid & 15) * 2;       // 0..30; items c,c+1, c+32,c+33

        u64 acc[4][2];                       // [o][pair]: p0=(c,c+1) p1=(+32)
#pragma unroll
        for (int oo = 0; oo < 4; ++oo) {
            const float b = b3[o0 + oo];
            const u64 pb = pk2(b, b);
            acc[oo][0] = pb; acc[oo][1] = pb;
        }

#pragma unroll 4
        for (int k = 0; k < 128; ++k) {
            const float4 a = *reinterpret_cast<const float4*>(g_W3t + k * 64 + o0);
            const u64 d0 = *reinterpret_cast<const u64*>(H2s + k * HSTR + c);
            const u64 d1 = *reinterpret_cast<const u64*>(H2s + k * HSTR + c + 32);
            const u64 ax = pk2(a.x, a.x);
            const u64 ay = pk2(a.y, a.y);
            const u64 az = pk2(a.z, a.z);
            const u64 aw = pk2(a.w, a.w);
            acc[0][0] = fma2(ax, d0, acc[0][0]); acc[0][1] = fma2(ax, d1, acc[0][1]);
            acc[1][0] = fma2(ay, d0, acc[1][0]); acc[1][1] = fma2(ay, d1, acc[1][1]);
            acc[2][0] = fma2(az, d0, acc[2][0]); acc[2][1] = fma2(az, d1, acc[2][1]);
            acc[3][0] = fma2(aw, d0, acc[3][0]); acc[3][1] = fma2(aw, d1, acc[3][1]);
        }

        // relu + partial layer4 dot over this thread's 4 o's
        const float4 w4 = *reinterpret_cast<const float4*>(W4 + o0);
        const int og = tid >> 4;             // 0..15
        const float2 v00 = up2(acc[0][0]); const float2 v01 = up2(acc[0][1]);
        const float2 v10 = up2(acc[1][0]); const float2 v11 = up2(acc[1][1]);
        const float2 v20 = up2(acc[2][0]); const float2 v21 = up2(acc[2][1]);
        const float2 v30 = up2(acc[3][0]); const float2 v31 = up2(acc[3][1]);

        float2 pa, pb;
        pa.x = __fmul_rn(w4.x, fmaxf(v00.x, 0.f));
        pa.x = fmaf(w4.y, fmaxf(v10.x, 0.f), pa.x);
        pa.x = fmaf(w4.z, fmaxf(v20.x, 0.f), pa.x);
        pa.x = fmaf(w4.w, fmaxf(v30.x, 0.f), pa.x);
        pa.y = __fmul_rn(w4.x, fmaxf(v00.y, 0.f));
        pa.y = fmaf(w4.y, fmaxf(v10.y, 0.f), pa.y);
        pa.y = fmaf(w4.z, fmaxf(v20.y, 0.f), pa.y);
        pa.y = fmaf(w4.w, fmaxf(v30.y, 0.f), pa.y);
        pb.x = __fmul_rn(w4.x, fmaxf(v01.x, 0.f));
        pb.x = fmaf(w4.y, fmaxf(v11.x, 0.f), pb.x);
        pb.x = fmaf(w4.z, fmaxf(v21.x, 0.f), pb.x);
        pb.x = fmaf(w4.w, fmaxf(v31.x, 0.f), pb.x);
        pb.y = __fmul_rn(w4.x, fmaxf(v01.y, 0.f));
        pb.y = fmaf(w4.y, fmaxf(v11.y, 0.f), pb.y);
        pb.y = fmaf(w4.z, fmaxf(v21.y, 0.f), pb.y);
        pb.y = fmaf(w4.w, fmaxf(v31.y, 0.f), pb.y);

        __syncthreads();   // all H2s reads done before red (aliases H1s) writes
        *reinterpret_cast<float2*>(red + og * HSTR + c)      = pa;  // conflict-free
        *reinterpret_cast<float2*>(red + og * HSTR + c + 32) = pb;  // conflict-free
    }
    __syncthreads();

    // final: one thread per item sums 16 partials
    if (tid < TILE_I) {
        const int item = blockIdx.x * TILE_I + tid;
        float s = red[tid];
#pragma unroll
        for (int g = 1; g < 16; ++g) s += red[g * HSTR + tid];
        out[item] = (s + b4[0]) * masks[tid];
    }
}

extern "C" void kernel_launch(void* const* d_in, const int* in_sizes, int n_in,
                              void* d_out, int out_size) {
    const float* x  = (const float*)d_in[0];
    const float* r  = (const float*)d_in[1];
    const float* W1 = (const float*)d_in[2];
    const float* b1 = (const float*)d_in[3];
    const float* W2 = (const float*)d_in[4];
    const float* b2 = (const float*)d_in[5];
    const float* W3 = (const float*)d_in[6];
    const float* b3 = (const float*)d_in[7];
    const float* W4 = (const float*)d_in[8];
    const float* b4 = (const float*)d_in[9];
    float* out = (float*)d_out;

    cudaFuncSetAttribute(fused_mlp_kernel,
                         cudaFuncAttributeMaxDynamicSharedMemorySize, SMEM_BYTES);

    topk_fused_kernel<<<NAG + TGRID, T1>>>(x, W2, W3);
    fused_mlp_kernel<<<NITEMS / TILE_I, 256, SMEM_BYTES>>>(
        x, r, W1, b1, b2, b3, W4, b4, out);
}